// round 1
// baseline (speedup 1.0000x reference)
#include <cuda_runtime.h>
#include <cuda_bf16.h>
#include <math_constants.h>

// Problem shape (fixed by the dataset)
#define BB 8
#define HH 3
#define PP 4096
#define TP 256        // p-points per block (= blockDim.x)
#define TQ 1024       // q-points staged to shared per tile
#define NBLK ((PP / TP) * BB)   // 128 partial sums

// Per point: float4 {x, y, z, |x|^2} and float4 {d0, d1, d2, 0}
__device__ float4 g_packed[BB * PP * 2];
__device__ float  g_partial[NBLK];

// ---------------------------------------------------------------------------
// Prep: compute packed point data + signed plane distances d_h = n̂·x + c
// ---------------------------------------------------------------------------
__global__ void prep_kernel(const float* __restrict__ planes,
                            const float* __restrict__ pts) {
    int idx = blockIdx.x * blockDim.x + threadIdx.x;   // 0 .. B*P-1
    if (idx >= BB * PP) return;
    int b = idx / PP;

    float x = pts[idx * 3 + 0];
    float y = pts[idx * 3 + 1];
    float z = pts[idx * 3 + 2];

    float d[HH];
#pragma unroll
    for (int h = 0; h < HH; h++) {
        const float* pl = planes + (b * HH + h) * 4;
        float nx = pl[0], ny = pl[1], nz = pl[2], c = pl[3];
        float nn  = nx * nx + ny * ny + nz * nz;
        float inv = rsqrtf(nn);
        inv = inv * (1.5f - 0.5f * nn * inv * inv);   // Newton refine
        d[h] = (nx * x + ny * y + nz * z) * inv + c;
    }

    g_packed[idx * 2 + 0] = make_float4(x, y, z, x * x + y * y + z * z);
    g_packed[idx * 2 + 1] = make_float4(d[0], d[1], d[2], 0.0f);
}

// ---------------------------------------------------------------------------
// Main: per (b, p) find min_q [ |x_p-x_q|^2 + 4 d_p^h d_q^h ] for 3 heads.
// Inner loop: 2x LDS.128 (broadcast) + 6 FFMA + 3 FMNMX per q.
// |x_p|^2 is folded out of the loop (added after min; clamp after).
// ---------------------------------------------------------------------------
__global__ __launch_bounds__(TP)
void chamfer_kernel() {
    __shared__ float4 sq[TQ * 2];
    __shared__ float  red[TP];

    const int b = blockIdx.y;
    const int p = blockIdx.x * TP + threadIdx.x;

    float4 a  = g_packed[(b * PP + p) * 2 + 0];
    float4 dd = g_packed[(b * PP + p) * 2 + 1];

    const float mx = -2.0f * a.x, my = -2.0f * a.y, mz = -2.0f * a.z;
    const float x2p = a.w;
    const float dp0 = 4.0f * dd.x, dp1 = 4.0f * dd.y, dp2 = 4.0f * dd.z;

    float m0 = CUDART_INF_F, m1 = CUDART_INF_F, m2 = CUDART_INF_F;

    const float4* __restrict__ base = g_packed + (size_t)b * PP * 2;

    for (int qt = 0; qt < PP; qt += TQ) {
        __syncthreads();
#pragma unroll
        for (int i = 0; i < (TQ * 2) / TP; i++) {
            int j = threadIdx.x + i * TP;
            sq[j] = base[qt * 2 + j];
        }
        __syncthreads();

#pragma unroll 8
        for (int qi = 0; qi < TQ; qi++) {
            float4 qa = sq[qi * 2 + 0];
            float4 qb = sq[qi * 2 + 1];
            float acc = fmaf(mx, qa.x, qa.w);   // x2q - 2*xp·xq (building)
            acc = fmaf(my, qa.y, acc);
            acc = fmaf(mz, qa.z, acc);
            m0 = fminf(m0, fmaf(dp0, qb.x, acc));
            m1 = fminf(m1, fmaf(dp1, qb.y, acc));
            m2 = fminf(m2, fmaf(dp2, qb.z, acc));
        }
    }

    // add the folded-out |x_p|^2, clamp at 0 (commutes with min), sum heads
    float s = fmaxf(m0 + x2p, 0.0f)
            + fmaxf(m1 + x2p, 0.0f)
            + fmaxf(m2 + x2p, 0.0f);

    // deterministic block tree-reduce
    red[threadIdx.x] = s;
    __syncthreads();
#pragma unroll
    for (int off = TP / 2; off > 0; off >>= 1) {
        if (threadIdx.x < off) red[threadIdx.x] += red[threadIdx.x + off];
        __syncthreads();
    }
    if (threadIdx.x == 0)
        g_partial[blockIdx.y * (PP / TP) + blockIdx.x] = red[0];
}

// ---------------------------------------------------------------------------
// Finalize: sum partials (double, fixed order = deterministic) + reg loss.
// ---------------------------------------------------------------------------
__global__ void finalize_kernel(const float* __restrict__ planes,
                                float* __restrict__ out) {
    if (threadIdx.x != 0) return;

    double s = 0.0;
    for (int i = 0; i < NBLK; i++) s += (double)g_partial[i];
    // refl = sum_h [cham_x + cham_y] = sum_h 2 * mean_{b,p} min  (symmetry)
    double refl = 2.0 * s / (double)(BB * PP);

    double reg = 0.0;
    for (int b = 0; b < BB; b++) {
        double n[HH][3];
        for (int h = 0; h < HH; h++) {
            const float* pl = planes + (b * HH + h) * 4;
            double nx = pl[0], ny = pl[1], nz = pl[2];
            double inv = 1.0 / sqrt(nx * nx + ny * ny + nz * nz);
            n[h][0] = nx * inv; n[h][1] = ny * inv; n[h][2] = nz * inv;
        }
        double acc = 0.0;
        for (int i = 0; i < HH; i++)
            for (int j = 0; j < HH; j++) {
                double g = n[i][0] * n[j][0] + n[i][1] * n[j][1]
                         + n[i][2] * n[j][2] - (i == j ? 1.0 : 0.0);
                acc += g * g;
            }
        reg += sqrt(acc);
    }

    out[0] = (float)(refl + 25.0 * reg);
}

// ---------------------------------------------------------------------------
extern "C" void kernel_launch(void* const* d_in, const int* in_sizes, int n_in,
                              void* d_out, int out_size) {
    const float* planes = (const float*)d_in[0];   // (8, 3, 4)
    const float* pts    = (const float*)d_in[1];   // (8, 4096, 3)
    // d_in[2], d_in[3] (voxel/cp grids) are unused by the reference.

    prep_kernel<<<(BB * PP + 255) / 256, 256>>>(planes, pts);

    dim3 grid(PP / TP, BB);
    chamfer_kernel<<<grid, TP>>>();

    finalize_kernel<<<1, 32>>>(planes, (float*)d_out);
}

// round 2
// speedup vs baseline: 1.2563x; 1.2563x over previous
#include <cuda_runtime.h>
#include <cuda_bf16.h>
#include <math_constants.h>

// Problem shape (fixed by the dataset)
#define BB 8
#define HH 3
#define PP 4096
#define NS 4                   // q-splits per batch
#define TPQ (PP / NS)          // 1024 q points per split
#define NPAIR (TPQ / 2)        // 512 packed q-pairs per split
#define TP 128                 // threads per chamfer block (each does 2 p)
#define NBLK 128               // combine partial sums

// Packed per-point data: float4 {x,y,z,|x|^2}, float4 {d0,d1,d2,0}
__device__ float4 g_packed[BB * PP * 2];
// q-pair packed SoA: per pair j: A={(x0,x1),(y0,y1)} B={(z0,z1),(w0,w1)}
//                    C={(d00,d01),(d10,d11)}          D={(d20,d21)}
__device__ ulonglong2         g_A[BB * PP / 2];
__device__ ulonglong2         g_B[BB * PP / 2];
__device__ ulonglong2         g_C[BB * PP / 2];
__device__ unsigned long long g_D[BB * PP / 2];
// per-split per-head partial mins: [s][h][b*PP+p]
__device__ float g_mins[NS * HH * BB * PP];
__device__ float g_partial[NBLK];

// ---- f32x2 helpers (Blackwell packed fp32) --------------------------------
__device__ __forceinline__ unsigned long long pack2(float lo, float hi) {
    unsigned long long d;
    asm("mov.b64 %0, {%1, %2};" : "=l"(d) : "f"(lo), "f"(hi));
    return d;
}
__device__ __forceinline__ unsigned long long fma2(unsigned long long a,
                                                   unsigned long long b,
                                                   unsigned long long c) {
    unsigned long long d;
    asm("fma.rn.f32x2 %0, %1, %2, %3;" : "=l"(d) : "l"(a), "l"(b), "l"(c));
    return d;
}
__device__ __forceinline__ void min2(float& a, float& b, unsigned long long t) {
    float lo, hi;
    asm("mov.b64 {%0, %1}, %2;" : "=f"(lo), "=f"(hi) : "l"(t));
    a = fminf(a, lo);
    b = fminf(b, hi);
}

// ---------------------------------------------------------------------------
// Prep: one thread per q-PAIR. Computes packed point data + plane distances.
// ---------------------------------------------------------------------------
__global__ void prep_kernel(const float* __restrict__ planes,
                            const float* __restrict__ pts) {
    int idx = blockIdx.x * blockDim.x + threadIdx.x;   // 0 .. B*P/2-1
    if (idx >= BB * PP / 2) return;
    int b  = idx / (PP / 2);
    int q0 = idx * 2;            // global point index (contiguous across b)

    float x0 = pts[q0 * 3 + 0], y0 = pts[q0 * 3 + 1], z0 = pts[q0 * 3 + 2];
    float x1 = pts[q0 * 3 + 3], y1 = pts[q0 * 3 + 4], z1 = pts[q0 * 3 + 5];
    float w0 = x0 * x0 + y0 * y0 + z0 * z0;
    float w1 = x1 * x1 + y1 * y1 + z1 * z1;

    float d0[HH], d1[HH];
#pragma unroll
    for (int h = 0; h < HH; h++) {
        const float* pl = planes + (b * HH + h) * 4;
        float nx = pl[0], ny = pl[1], nz = pl[2], c = pl[3];
        float nn  = nx * nx + ny * ny + nz * nz;
        float inv = rsqrtf(nn);
        inv = inv * (1.5f - 0.5f * nn * inv * inv);   // Newton refine
        d0[h] = (nx * x0 + ny * y0 + nz * z0) * inv + c;
        d1[h] = (nx * x1 + ny * y1 + nz * z1) * inv + c;
    }

    g_packed[q0 * 2 + 0] = make_float4(x0, y0, z0, w0);
    g_packed[q0 * 2 + 1] = make_float4(d0[0], d0[1], d0[2], 0.0f);
    g_packed[q0 * 2 + 2] = make_float4(x1, y1, z1, w1);
    g_packed[q0 * 2 + 3] = make_float4(d1[0], d1[1], d1[2], 0.0f);

    ulonglong2 A, B, C;
    A.x = pack2(x0, x1);      A.y = pack2(y0, y1);
    B.x = pack2(z0, z1);      B.y = pack2(w0, w1);
    C.x = pack2(d0[0], d1[0]); C.y = pack2(d0[1], d1[1]);
    g_A[idx] = A;
    g_B[idx] = B;
    g_C[idx] = C;
    g_D[idx] = pack2(d0[2], d1[2]);
}

// ---------------------------------------------------------------------------
// Main: block = (p-tile of 256, q-split of 1024, batch).
// Each thread handles 2 p-points; inner loop processes a packed q-pair with
// FFMA2 (f32x2): 4 LDS + 12 FFMA2 + 12 FMNMX per 4 pair-evals.
// ---------------------------------------------------------------------------
__global__ __launch_bounds__(TP)
void chamfer_kernel() {
    __shared__ ulonglong2         sA[NPAIR];
    __shared__ ulonglong2         sB[NPAIR];
    __shared__ ulonglong2         sC[NPAIR];
    __shared__ unsigned long long sD[NPAIR];

    const int t    = threadIdx.x;
    const int tile = blockIdx.x;        // 0..15
    const int spl  = blockIdx.y;        // 0..NS-1
    const int b    = blockIdx.z;        // 0..7

    // stage this split's q-pairs
    const int qbase = b * (PP / 2) + spl * NPAIR;
    for (int j = t; j < NPAIR; j += TP) {
        sA[j] = g_A[qbase + j];
        sB[j] = g_B[qbase + j];
        sC[j] = g_C[qbase + j];
        sD[j] = g_D[qbase + j];
    }

    // per-thread p constants (2 p-points, stride TP apart)
    const int p0 = tile * (2 * TP) + t;
    const int p1 = p0 + TP;
    float4 a0  = g_packed[(b * PP + p0) * 2 + 0];
    float4 dd0 = g_packed[(b * PP + p0) * 2 + 1];
    float4 a1  = g_packed[(b * PP + p1) * 2 + 0];
    float4 dd1 = g_packed[(b * PP + p1) * 2 + 1];

    const unsigned long long MX0 = pack2(-2.f * a0.x, -2.f * a0.x);
    const unsigned long long MY0 = pack2(-2.f * a0.y, -2.f * a0.y);
    const unsigned long long MZ0 = pack2(-2.f * a0.z, -2.f * a0.z);
    const unsigned long long P00 = pack2(4.f * dd0.x, 4.f * dd0.x);
    const unsigned long long P01 = pack2(4.f * dd0.y, 4.f * dd0.y);
    const unsigned long long P02 = pack2(4.f * dd0.z, 4.f * dd0.z);
    const unsigned long long MX1 = pack2(-2.f * a1.x, -2.f * a1.x);
    const unsigned long long MY1 = pack2(-2.f * a1.y, -2.f * a1.y);
    const unsigned long long MZ1 = pack2(-2.f * a1.z, -2.f * a1.z);
    const unsigned long long P10 = pack2(4.f * dd1.x, 4.f * dd1.x);
    const unsigned long long P11 = pack2(4.f * dd1.y, 4.f * dd1.y);
    const unsigned long long P12 = pack2(4.f * dd1.z, 4.f * dd1.z);

    float m00a = CUDART_INF_F, m00b = CUDART_INF_F;
    float m01a = CUDART_INF_F, m01b = CUDART_INF_F;
    float m02a = CUDART_INF_F, m02b = CUDART_INF_F;
    float m10a = CUDART_INF_F, m10b = CUDART_INF_F;
    float m11a = CUDART_INF_F, m11b = CUDART_INF_F;
    float m12a = CUDART_INF_F, m12b = CUDART_INF_F;

    __syncthreads();

#pragma unroll 4
    for (int j = 0; j < NPAIR; j++) {
        ulonglong2 A = sA[j];
        ulonglong2 B = sB[j];
        ulonglong2 C = sC[j];
        unsigned long long D2 = sD[j];

        // acc = w_q - 2 x_p . x_q   (|x_p|^2 folded out, added in combine)
        unsigned long long acc0 = fma2(MX0, A.x, B.y);
        acc0 = fma2(MY0, A.y, acc0);
        acc0 = fma2(MZ0, B.x, acc0);
        min2(m00a, m00b, fma2(P00, C.x, acc0));
        min2(m01a, m01b, fma2(P01, C.y, acc0));
        min2(m02a, m02b, fma2(P02, D2,  acc0));

        unsigned long long acc1 = fma2(MX1, A.x, B.y);
        acc1 = fma2(MY1, A.y, acc1);
        acc1 = fma2(MZ1, B.x, acc1);
        min2(m10a, m10b, fma2(P10, C.x, acc1));
        min2(m11a, m11b, fma2(P11, C.y, acc1));
        min2(m12a, m12b, fma2(P12, D2,  acc1));
    }

    // fold q-parity halves, write per-split per-head mins
    const int i0 = b * PP + p0;
    const int i1 = b * PP + p1;
    const int N  = BB * PP;
    g_mins[(spl * HH + 0) * N + i0] = fminf(m00a, m00b);
    g_mins[(spl * HH + 1) * N + i0] = fminf(m01a, m01b);
    g_mins[(spl * HH + 2) * N + i0] = fminf(m02a, m02b);
    g_mins[(spl * HH + 0) * N + i1] = fminf(m10a, m10b);
    g_mins[(spl * HH + 1) * N + i1] = fminf(m11a, m11b);
    g_mins[(spl * HH + 2) * N + i1] = fminf(m12a, m12b);
}

// ---------------------------------------------------------------------------
// Combine: min across splits, add |x_p|^2, clamp, sum heads, block-reduce.
// ---------------------------------------------------------------------------
__global__ __launch_bounds__(256)
void combine_kernel() {
    __shared__ float red[256];
    const int i = blockIdx.x * 256 + threadIdx.x;   // 0 .. B*P-1
    const int N = BB * PP;

    float x2p = g_packed[i * 2].w;
    float s = 0.0f;
#pragma unroll
    for (int h = 0; h < HH; h++) {
        float m = g_mins[(0 * HH + h) * N + i];
#pragma unroll
        for (int sp = 1; sp < NS; sp++)
            m = fminf(m, g_mins[(sp * HH + h) * N + i]);
        s += fmaxf(m + x2p, 0.0f);
    }

    red[threadIdx.x] = s;
    __syncthreads();
#pragma unroll
    for (int off = 128; off > 0; off >>= 1) {
        if (threadIdx.x < off) red[threadIdx.x] += red[threadIdx.x + off];
        __syncthreads();
    }
    if (threadIdx.x == 0) g_partial[blockIdx.x] = red[0];
}

// ---------------------------------------------------------------------------
// Finalize: deterministic double-precision sum + regularization loss.
// ---------------------------------------------------------------------------
__global__ void finalize_kernel(const float* __restrict__ planes,
                                float* __restrict__ out) {
    if (threadIdx.x != 0) return;

    double s = 0.0;
    for (int i = 0; i < NBLK; i++) s += (double)g_partial[i];
    double refl = 2.0 * s / (double)(BB * PP);   // cham_x == cham_y by symmetry

    double reg = 0.0;
    for (int b = 0; b < BB; b++) {
        double n[HH][3];
        for (int h = 0; h < HH; h++) {
            const float* pl = planes + (b * HH + h) * 4;
            double nx = pl[0], ny = pl[1], nz = pl[2];
            double inv = 1.0 / sqrt(nx * nx + ny * ny + nz * nz);
            n[h][0] = nx * inv; n[h][1] = ny * inv; n[h][2] = nz * inv;
        }
        double acc = 0.0;
        for (int i = 0; i < HH; i++)
            for (int j = 0; j < HH; j++) {
                double g = n[i][0] * n[j][0] + n[i][1] * n[j][1]
                         + n[i][2] * n[j][2] - (i == j ? 1.0 : 0.0);
                acc += g * g;
            }
        reg += sqrt(acc);
    }

    out[0] = (float)(refl + 25.0 * reg);
}

// ---------------------------------------------------------------------------
extern "C" void kernel_launch(void* const* d_in, const int* in_sizes, int n_in,
                              void* d_out, int out_size) {
    const float* planes = (const float*)d_in[0];   // (8, 3, 4)
    const float* pts    = (const float*)d_in[1];   // (8, 4096, 3)
    // d_in[2], d_in[3] (voxel/cp grids) are unused by the reference.

    prep_kernel<<<(BB * PP / 2 + 255) / 256, 256>>>(planes, pts);

    dim3 grid(PP / (2 * TP), NS, BB);   // (16, 4, 8)
    chamfer_kernel<<<grid, TP>>>();

    combine_kernel<<<NBLK, 256>>>();
    finalize_kernel<<<1, 32>>>(planes, (float*)d_out);
}

// round 3
// speedup vs baseline: 2.2493x; 1.7904x over previous
#include <cuda_runtime.h>
#include <cuda_bf16.h>
#include <math_constants.h>

// Problem shape (fixed by the dataset)
#define BB 8
#define HH 3
#define PP 4096
#define NS 8                    // q-splits per batch
#define TPQ (PP / NS)           // 512 q points per split
#define NPAIR (TPQ / 2)         // 256 packed q-pairs per split
#define TP 128                  // threads per chamfer block (each does 2 p)
#define NBLK 128                // combine partial sums

// per-split per-head partial mins: [s][h][b*PP+p]
__device__ float g_mins[NS * HH * BB * PP];
__device__ float g_partial[NBLK];

// ---- f32x2 helpers (Blackwell packed fp32) --------------------------------
__device__ __forceinline__ unsigned long long pack2(float lo, float hi) {
    unsigned long long d;
    asm("mov.b64 %0, {%1, %2};" : "=l"(d) : "f"(lo), "f"(hi));
    return d;
}
__device__ __forceinline__ unsigned long long fma2(unsigned long long a,
                                                   unsigned long long b,
                                                   unsigned long long c) {
    unsigned long long d;
    asm("fma.rn.f32x2 %0, %1, %2, %3;" : "=l"(d) : "l"(a), "l"(b), "l"(c));
    return d;
}
__device__ __forceinline__ void min2(float& a, float& b, unsigned long long t) {
    float lo, hi;
    asm("mov.b64 {%0, %1}, %2;" : "=f"(lo), "=f"(hi) : "l"(t));
    a = fminf(a, lo);
    b = fminf(b, hi);
}

// normalized plane normals + offset for batch b (fp32, Newton-refined rsqrt)
__device__ __forceinline__ void load_normals(const float* __restrict__ planes,
                                             int b, float nx[HH], float ny[HH],
                                             float nz[HH], float nc[HH]) {
#pragma unroll
    for (int h = 0; h < HH; h++) {
        const float* pl = planes + (b * HH + h) * 4;
        float x = pl[0], y = pl[1], z = pl[2];
        float nn  = x * x + y * y + z * z;
        float inv = rsqrtf(nn);
        inv = inv * (1.5f - 0.5f * nn * inv * inv);
        nx[h] = x * inv; ny[h] = y * inv; nz[h] = z * inv; nc[h] = pl[3];
    }
}

// ---------------------------------------------------------------------------
// Main kernel: block = (p-tile of 256, q-split of 512, batch).
// Stages its own q-tile (computing w and plane distances inline), then runs
// the FFMA2 inner loop: 4 LDS + 12 FFMA2 + 12 FMNMX per (2p x 2q x 3heads).
// ---------------------------------------------------------------------------
__global__ __launch_bounds__(TP)
void chamfer_kernel(const float* __restrict__ planes,
                    const float* __restrict__ pts) {
    // per pair j: sA={(x0,x1),(y0,y1)}  sB={(z0,z1),(w0,w1)}
    //             sC={(d00,d01),(d10,d11)}  sD={(d20,d21)}
    __shared__ ulonglong2         sA[NPAIR];
    __shared__ ulonglong2         sB[NPAIR];
    __shared__ ulonglong2         sC[NPAIR];
    __shared__ unsigned long long sD[NPAIR];

    const int t    = threadIdx.x;
    const int tile = blockIdx.x;        // 0..15
    const int spl  = blockIdx.y;        // 0..NS-1
    const int b    = blockIdx.z;        // 0..7

    float nx[HH], ny[HH], nz[HH], nc[HH];
    load_normals(planes, b, nx, ny, nz, nc);

    // ---- stage q-tile: NPAIR pairs, each thread does NPAIR/TP pairs ----
    const int qstart = b * PP + spl * TPQ;      // global point index
#pragma unroll
    for (int j = t; j < NPAIR; j += TP) {
        const float* q = pts + (qstart + 2 * j) * 3;
        float x0 = q[0], y0 = q[1], z0 = q[2];
        float x1 = q[3], y1 = q[4], z1 = q[5];
        float w0 = x0 * x0 + y0 * y0 + z0 * z0;
        float w1 = x1 * x1 + y1 * y1 + z1 * z1;
        float d0[HH], d1[HH];
#pragma unroll
        for (int h = 0; h < HH; h++) {
            d0[h] = nx[h] * x0 + ny[h] * y0 + nz[h] * z0 + nc[h];
            d1[h] = nx[h] * x1 + ny[h] * y1 + nz[h] * z1 + nc[h];
        }
        ulonglong2 A, B, C;
        A.x = pack2(x0, x1);       A.y = pack2(y0, y1);
        B.x = pack2(z0, z1);       B.y = pack2(w0, w1);
        C.x = pack2(d0[0], d1[0]); C.y = pack2(d0[1], d1[1]);
        sA[j] = A; sB[j] = B; sC[j] = C;
        sD[j] = pack2(d0[2], d1[2]);
    }

    // ---- per-thread p constants (2 p-points, stride TP apart) ----
    const int p0 = tile * (2 * TP) + t;
    const int p1 = p0 + TP;
    const float* P0 = pts + (b * PP + p0) * 3;
    const float* P1 = pts + (b * PP + p1) * 3;
    float ax0 = P0[0], ay0 = P0[1], az0 = P0[2];
    float ax1 = P1[0], ay1 = P1[1], az1 = P1[2];
    float e0[HH], e1[HH];
#pragma unroll
    for (int h = 0; h < HH; h++) {
        e0[h] = nx[h] * ax0 + ny[h] * ay0 + nz[h] * az0 + nc[h];
        e1[h] = nx[h] * ax1 + ny[h] * ay1 + nz[h] * az1 + nc[h];
    }

    const unsigned long long MX0 = pack2(-2.f * ax0, -2.f * ax0);
    const unsigned long long MY0 = pack2(-2.f * ay0, -2.f * ay0);
    const unsigned long long MZ0 = pack2(-2.f * az0, -2.f * az0);
    const unsigned long long Q00 = pack2(4.f * e0[0], 4.f * e0[0]);
    const unsigned long long Q01 = pack2(4.f * e0[1], 4.f * e0[1]);
    const unsigned long long Q02 = pack2(4.f * e0[2], 4.f * e0[2]);
    const unsigned long long MX1 = pack2(-2.f * ax1, -2.f * ax1);
    const unsigned long long MY1 = pack2(-2.f * ay1, -2.f * ay1);
    const unsigned long long MZ1 = pack2(-2.f * az1, -2.f * az1);
    const unsigned long long Q10 = pack2(4.f * e1[0], 4.f * e1[0]);
    const unsigned long long Q11 = pack2(4.f * e1[1], 4.f * e1[1]);
    const unsigned long long Q12 = pack2(4.f * e1[2], 4.f * e1[2]);

    float m00a = CUDART_INF_F, m00b = CUDART_INF_F;
    float m01a = CUDART_INF_F, m01b = CUDART_INF_F;
    float m02a = CUDART_INF_F, m02b = CUDART_INF_F;
    float m10a = CUDART_INF_F, m10b = CUDART_INF_F;
    float m11a = CUDART_INF_F, m11b = CUDART_INF_F;
    float m12a = CUDART_INF_F, m12b = CUDART_INF_F;

    __syncthreads();

#pragma unroll 4
    for (int j = 0; j < NPAIR; j++) {
        ulonglong2 A = sA[j];
        ulonglong2 B = sB[j];
        ulonglong2 C = sC[j];
        unsigned long long D2 = sD[j];

        // acc = w_q - 2 x_p . x_q   (|x_p|^2 folded out, added in combine)
        unsigned long long acc0 = fma2(MX0, A.x, B.y);
        acc0 = fma2(MY0, A.y, acc0);
        acc0 = fma2(MZ0, B.x, acc0);
        min2(m00a, m00b, fma2(Q00, C.x, acc0));
        min2(m01a, m01b, fma2(Q01, C.y, acc0));
        min2(m02a, m02b, fma2(Q02, D2,  acc0));

        unsigned long long acc1 = fma2(MX1, A.x, B.y);
        acc1 = fma2(MY1, A.y, acc1);
        acc1 = fma2(MZ1, B.x, acc1);
        min2(m10a, m10b, fma2(Q10, C.x, acc1));
        min2(m11a, m11b, fma2(Q11, C.y, acc1));
        min2(m12a, m12b, fma2(Q12, D2,  acc1));
    }

    // fold q-parity halves, write per-split per-head mins
    const int i0 = b * PP + p0;
    const int i1 = b * PP + p1;
    const int N  = BB * PP;
    g_mins[(spl * HH + 0) * N + i0] = fminf(m00a, m00b);
    g_mins[(spl * HH + 1) * N + i0] = fminf(m01a, m01b);
    g_mins[(spl * HH + 2) * N + i0] = fminf(m02a, m02b);
    g_mins[(spl * HH + 0) * N + i1] = fminf(m10a, m10b);
    g_mins[(spl * HH + 1) * N + i1] = fminf(m11a, m11b);
    g_mins[(spl * HH + 2) * N + i1] = fminf(m12a, m12b);
}

// ---------------------------------------------------------------------------
// Combine: min across splits, add |x_p|^2 (recomputed), clamp, sum heads,
// deterministic block tree-reduce.
// ---------------------------------------------------------------------------
__global__ __launch_bounds__(256)
void combine_kernel(const float* __restrict__ pts) {
    __shared__ float red[256];
    const int i = blockIdx.x * 256 + threadIdx.x;   // 0 .. B*P-1
    const int N = BB * PP;

    float x = pts[i * 3 + 0], y = pts[i * 3 + 1], z = pts[i * 3 + 2];
    float x2p = x * x + y * y + z * z;

    float s = 0.0f;
#pragma unroll
    for (int h = 0; h < HH; h++) {
        float m = g_mins[(0 * HH + h) * N + i];
#pragma unroll
        for (int sp = 1; sp < NS; sp++)
            m = fminf(m, g_mins[(sp * HH + h) * N + i]);
        s += fmaxf(m + x2p, 0.0f);
    }

    red[threadIdx.x] = s;
    __syncthreads();
#pragma unroll
    for (int off = 128; off > 0; off >>= 1) {
        if (threadIdx.x < off) red[threadIdx.x] += red[threadIdx.x + off];
        __syncthreads();
    }
    if (threadIdx.x == 0) g_partial[blockIdx.x] = red[0];
}

// ---------------------------------------------------------------------------
// Finalize: parallel fp32 tree-reduce of partials + per-batch reg loss.
// Deterministic (fixed tree order).
// ---------------------------------------------------------------------------
__global__ __launch_bounds__(128)
void finalize_kernel(const float* __restrict__ planes,
                     float* __restrict__ out) {
    __shared__ float red[128];
    __shared__ float regs[BB];
    const int t = threadIdx.x;

    red[t] = g_partial[t];
    __syncthreads();
#pragma unroll
    for (int off = 64; off > 0; off >>= 1) {
        if (t < off) red[t] += red[t + off];
        __syncthreads();
    }

    // threads 0..7: reg loss per batch (fp32)
    if (t < BB) {
        float nx[HH], ny[HH], nz[HH], nc[HH];
        load_normals(planes, t, nx, ny, nz, nc);
        float acc = 0.0f;
#pragma unroll
        for (int i = 0; i < HH; i++)
#pragma unroll
            for (int j = 0; j < HH; j++) {
                float g = nx[i] * nx[j] + ny[i] * ny[j] + nz[i] * nz[j]
                        - (i == j ? 1.0f : 0.0f);
                acc += g * g;
            }
        regs[t] = sqrtf(acc);
    }
    __syncthreads();

    if (t == 0) {
        float reg = 0.0f;
#pragma unroll
        for (int b = 0; b < BB; b++) reg += regs[b];
        // cham_x == cham_y by reflection symmetry -> factor 2
        float refl = 2.0f * red[0] / (float)(BB * PP);
        out[0] = refl + 25.0f * reg;
    }
}

// ---------------------------------------------------------------------------
extern "C" void kernel_launch(void* const* d_in, const int* in_sizes, int n_in,
                              void* d_out, int out_size) {
    const float* planes = (const float*)d_in[0];   // (8, 3, 4)
    const float* pts    = (const float*)d_in[1];   // (8, 4096, 3)
    // d_in[2], d_in[3] (voxel/cp grids) are unused by the reference.

    dim3 grid(PP / (2 * TP), NS, BB);   // (16, 8, 8) = 1024 blocks
    chamfer_kernel<<<grid, TP>>>(planes, pts);

    combine_kernel<<<NBLK, 256>>>(pts);
    finalize_kernel<<<1, 128>>>(planes, (float*)d_out);
}

// round 5
// speedup vs baseline: 2.3407x; 1.0407x over previous
#include <cuda_runtime.h>
#include <cuda_bf16.h>
#include <math_constants.h>

// Problem shape (fixed by the dataset)
#define BB 8
#define HH 3
#define PP 4096
#define NS 16                   // q-splits per batch
#define TPQ (PP / NS)           // 256 q points per split
#define NPAIR (TPQ / 2)         // 128 packed q-pairs per split
#define TP 128                  // threads per chamfer block
#define PPT 4                   // p-points per thread
#define PBLK (TP * PPT)         // 512 p per block
#define NBLK 128                // combine partial sums

// per-split per-head partial mins: [s][h][b*PP+p]
__device__ float g_mins[NS * HH * BB * PP];
__device__ float g_partial[NBLK];

// ---- f32x2 helpers (Blackwell packed fp32: add/sub/mul/fma only) ----------
__device__ __forceinline__ unsigned long long pack2(float lo, float hi) {
    unsigned long long d;
    asm("mov.b64 %0, {%1, %2};" : "=l"(d) : "f"(lo), "f"(hi));
    return d;
}
__device__ __forceinline__ unsigned long long fma2(unsigned long long a,
                                                   unsigned long long b,
                                                   unsigned long long c) {
    unsigned long long d;
    asm("fma.rn.f32x2 %0, %1, %2, %3;" : "=l"(d) : "l"(a), "l"(b), "l"(c));
    return d;
}
// scalar min of packed result into two scalar accumulators (mov.b64 unpack is
// register aliasing -> free; mins are 2x FMNMX on the alu pipe)
__device__ __forceinline__ void min2(float& a, float& b, unsigned long long t) {
    float lo, hi;
    asm("mov.b64 {%0, %1}, %2;" : "=f"(lo), "=f"(hi) : "l"(t));
    a = fminf(a, lo);
    b = fminf(b, hi);
}

// normalized plane normals + offset for batch b (fp32, Newton-refined rsqrt)
__device__ __forceinline__ void load_normals(const float* __restrict__ planes,
                                             int b, float nx[HH], float ny[HH],
                                             float nz[HH], float nc[HH]) {
#pragma unroll
    for (int h = 0; h < HH; h++) {
        const float* pl = planes + (b * HH + h) * 4;
        float x = pl[0], y = pl[1], z = pl[2];
        float nn  = x * x + y * y + z * z;
        float inv = rsqrtf(nn);
        inv = inv * (1.5f - 0.5f * nn * inv * inv);
        nx[h] = x * inv; ny[h] = y * inv; nz[h] = z * inv; nc[h] = pl[3];
    }
}

// ---------------------------------------------------------------------------
// Main kernel: block = (p-tile of 512, q-split of 256, batch).
// Inner loop per q-pair: 4 LDS.128 + 24 FFMA2 + 24 FMNMX covering 4p x 2q x 3h.
// ---------------------------------------------------------------------------
__global__ __launch_bounds__(TP)
void chamfer_kernel(const float* __restrict__ planes,
                    const float* __restrict__ pts) {
    // per pair j: sA={(x0,x1),(y0,y1)}  sB={(z0,z1),(w0,w1)}
    //             sC={(d00,d01),(d10,d11)}  sD={(d20,d21)}
    __shared__ ulonglong2         sA[NPAIR];
    __shared__ ulonglong2         sB[NPAIR];
    __shared__ ulonglong2         sC[NPAIR];
    __shared__ unsigned long long sD[NPAIR];

    const int t    = threadIdx.x;
    const int tile = blockIdx.x;        // 0 .. PP/PBLK-1
    const int spl  = blockIdx.y;        // 0 .. NS-1
    const int b    = blockIdx.z;        // 0 .. BB-1

    float nx[HH], ny[HH], nz[HH], nc[HH];
    load_normals(planes, b, nx, ny, nz, nc);

    // ---- stage q-tile (NPAIR = TP so each thread does one pair) ----
    const int qstart = b * PP + spl * TPQ;
#pragma unroll
    for (int j = t; j < NPAIR; j += TP) {
        const float* q = pts + (qstart + 2 * j) * 3;
        float x0 = q[0], y0 = q[1], z0 = q[2];
        float x1 = q[3], y1 = q[4], z1 = q[5];
        float w0 = x0 * x0 + y0 * y0 + z0 * z0;
        float w1 = x1 * x1 + y1 * y1 + z1 * z1;
        float d0[HH], d1[HH];
#pragma unroll
        for (int h = 0; h < HH; h++) {
            d0[h] = nx[h] * x0 + ny[h] * y0 + nz[h] * z0 + nc[h];
            d1[h] = nx[h] * x1 + ny[h] * y1 + nz[h] * z1 + nc[h];
        }
        ulonglong2 A, B, C;
        A.x = pack2(x0, x1);       A.y = pack2(y0, y1);
        B.x = pack2(z0, z1);       B.y = pack2(w0, w1);
        C.x = pack2(d0[0], d1[0]); C.y = pack2(d0[1], d1[1]);
        sA[j] = A; sB[j] = B; sC[j] = C;
        sD[j] = pack2(d0[2], d1[2]);
    }

    // ---- per-thread p constants: PPT p-points, stride TP apart ----
    unsigned long long MX[PPT], MY[PPT], MZ[PPT];
    unsigned long long Q0[PPT], Q1[PPT], Q2[PPT];
    float m0a[PPT], m0b[PPT], m1a[PPT], m1b[PPT], m2a[PPT], m2b[PPT];
#pragma unroll
    for (int k = 0; k < PPT; k++) {
        const int p = tile * PBLK + k * TP + t;
        const float* P = pts + (b * PP + p) * 3;
        float ax = P[0], ay = P[1], az = P[2];
        float e0 = nx[0] * ax + ny[0] * ay + nz[0] * az + nc[0];
        float e1 = nx[1] * ax + ny[1] * ay + nz[1] * az + nc[1];
        float e2 = nx[2] * ax + ny[2] * ay + nz[2] * az + nc[2];
        MX[k] = pack2(-2.f * ax, -2.f * ax);
        MY[k] = pack2(-2.f * ay, -2.f * ay);
        MZ[k] = pack2(-2.f * az, -2.f * az);
        Q0[k] = pack2(4.f * e0, 4.f * e0);
        Q1[k] = pack2(4.f * e1, 4.f * e1);
        Q2[k] = pack2(4.f * e2, 4.f * e2);
        m0a[k] = m0b[k] = CUDART_INF_F;
        m1a[k] = m1b[k] = CUDART_INF_F;
        m2a[k] = m2b[k] = CUDART_INF_F;
    }

    __syncthreads();

#pragma unroll 8
    for (int j = 0; j < NPAIR; j++) {
        ulonglong2 A = sA[j];
        ulonglong2 B = sB[j];
        ulonglong2 C = sC[j];
        unsigned long long D2 = sD[j];

#pragma unroll
        for (int k = 0; k < PPT; k++) {
            // acc = w_q - 2 x_p . x_q   (|x_p|^2 folded out, added in combine)
            unsigned long long acc = fma2(MX[k], A.x, B.y);
            acc = fma2(MY[k], A.y, acc);
            acc = fma2(MZ[k], B.x, acc);
            min2(m0a[k], m0b[k], fma2(Q0[k], C.x, acc));
            min2(m1a[k], m1b[k], fma2(Q1[k], C.y, acc));
            min2(m2a[k], m2b[k], fma2(Q2[k], D2,  acc));
        }
    }

    // fold packed halves, write per-split per-head mins
    const int N = BB * PP;
#pragma unroll
    for (int k = 0; k < PPT; k++) {
        const int i = b * PP + tile * PBLK + k * TP + t;
        g_mins[(spl * HH + 0) * N + i] = fminf(m0a[k], m0b[k]);
        g_mins[(spl * HH + 1) * N + i] = fminf(m1a[k], m1b[k]);
        g_mins[(spl * HH + 2) * N + i] = fminf(m2a[k], m2b[k]);
    }
}

// ---------------------------------------------------------------------------
// Combine: min across splits, add |x_p|^2 (recomputed), clamp, sum heads,
// deterministic block tree-reduce.
// ---------------------------------------------------------------------------
__global__ __launch_bounds__(256)
void combine_kernel(const float* __restrict__ pts) {
    __shared__ float red[256];
    const int i = blockIdx.x * 256 + threadIdx.x;   // 0 .. B*P-1
    const int N = BB * PP;

    float x = pts[i * 3 + 0], y = pts[i * 3 + 1], z = pts[i * 3 + 2];
    float x2p = x * x + y * y + z * z;

    float s = 0.0f;
#pragma unroll
    for (int h = 0; h < HH; h++) {
        float m = g_mins[(0 * HH + h) * N + i];
#pragma unroll
        for (int sp = 1; sp < NS; sp++)
            m = fminf(m, g_mins[(sp * HH + h) * N + i]);
        s += fmaxf(m + x2p, 0.0f);
    }

    red[threadIdx.x] = s;
    __syncthreads();
#pragma unroll
    for (int off = 128; off > 0; off >>= 1) {
        if (threadIdx.x < off) red[threadIdx.x] += red[threadIdx.x + off];
        __syncthreads();
    }
    if (threadIdx.x == 0) g_partial[blockIdx.x] = red[0];
}

// ---------------------------------------------------------------------------
// Finalize: parallel fp32 tree-reduce of partials + per-batch reg loss.
// ---------------------------------------------------------------------------
__global__ __launch_bounds__(128)
void finalize_kernel(const float* __restrict__ planes,
                     float* __restrict__ out) {
    __shared__ float red[128];
    __shared__ float regs[BB];
    const int t = threadIdx.x;

    red[t] = g_partial[t];
    __syncthreads();
#pragma unroll
    for (int off = 64; off > 0; off >>= 1) {
        if (t < off) red[t] += red[t + off];
        __syncthreads();
    }

    if (t < BB) {
        float nx[HH], ny[HH], nz[HH], nc[HH];
        load_normals(planes, t, nx, ny, nz, nc);
        float acc = 0.0f;
#pragma unroll
        for (int i = 0; i < HH; i++)
#pragma unroll
            for (int j = 0; j < HH; j++) {
                float g = nx[i] * nx[j] + ny[i] * ny[j] + nz[i] * nz[j]
                        - (i == j ? 1.0f : 0.0f);
                acc += g * g;
            }
        regs[t] = sqrtf(acc);
    }
    __syncthreads();

    if (t == 0) {
        float reg = 0.0f;
#pragma unroll
        for (int b = 0; b < BB; b++) reg += regs[b];
        // cham_x == cham_y by reflection symmetry -> factor 2
        float refl = 2.0f * red[0] / (float)(BB * PP);
        out[0] = refl + 25.0f * reg;
    }
}

// ---------------------------------------------------------------------------
extern "C" void kernel_launch(void* const* d_in, const int* in_sizes, int n_in,
                              void* d_out, int out_size) {
    const float* planes = (const float*)d_in[0];   // (8, 3, 4)
    const float* pts    = (const float*)d_in[1];   // (8, 4096, 3)
    // d_in[2], d_in[3] (voxel/cp grids) are unused by the reference.

    dim3 grid(PP / PBLK, NS, BB);   // (8, 16, 8) = 1024 blocks
    chamfer_kernel<<<grid, TP>>>(planes, pts);

    combine_kernel<<<NBLK, 256>>>(pts);
    finalize_kernel<<<1, 128>>>(planes, (float*)d_out);
}